// round 5
// baseline (speedup 1.0000x reference)
#include <cuda_runtime.h>
#include <math.h>

#define NN 20000
#define EE 320000
#define ET 340000   // EE + NN self loops
#define BG 32
#define FH 256      // H*C
#define HH 4
#define CC 64

typedef unsigned long long ull;

// ---------------- packed f32x2 helpers (FFMA2 — 2x fp32 FMA throughput) -----
__device__ __forceinline__ void fma2(ull &d, ull a, ull b) {
    asm("fma.rn.f32x2 %0, %1, %2, %0;" : "+l"(d) : "l"(a), "l"(b));
}
__device__ __forceinline__ ull add2(ull a, ull b) {
    ull r; asm("add.rn.f32x2 %0, %1, %2;" : "=l"(r) : "l"(a), "l"(b)); return r;
}
__device__ __forceinline__ ull dup2(float x) {
    ull r; asm("mov.b64 %0, {%1, %1};" : "=l"(r) : "f"(x)); return r;
}
__device__ __forceinline__ void unpack2(ull v, float &lo, float &hi) {
    asm("mov.b64 {%0, %1}, %2;" : "=f"(lo), "=f"(hi) : "l"(v));
}

// ---------------- scratch (device globals; no allocation allowed) ----------
__device__ __align__(16) float g_buf1[NN * FH];   // GEMM output (h)
__device__ __align__(16) float g_buf2[NN * FH];   // aggregation output
__device__ __align__(16) float g_as[NN * HH];
__device__ __align__(16) float g_ad[NN * HH];
__device__ __align__(16) int   g_deg[NN];
__device__ __align__(16) int   g_rowptr[NN + 1];
__device__ int   g_cursor[NN];
__device__ int   g_col[ET];
__device__ float g_pool[BG * FH];
__device__ int   g_cnt[BG];

// ---------------- init: deg=1 (self loop), zero pool/cnt --------------------
__global__ void init_zero_kernel() {
    int n = blockIdx.x * blockDim.x + threadIdx.x;
    if (n < NN) g_deg[n] = 1;
    if (n < BG * FH) g_pool[n] = 0.f;
    if (n < BG) g_cnt[n] = 0;
}

__global__ void hist_kernel(const int* __restrict__ ei) {
    int e = blockIdx.x * blockDim.x + threadIdx.x;
    if (e >= EE) return;
    int dst = ei[EE + e];
    atomicAdd(&g_deg[dst], 1);
}

// exclusive scan over g_deg + fused self-loop/cursor init, single block
__global__ void scan_selfloop_kernel() {
    __shared__ int wsum[32];
    int tid = threadIdx.x;
    int lane = tid & 31, wid = tid >> 5;
    int4 v[5];
    int sum = 0;
    if (tid < 1000) {               // 1000 * 20 = 20000 exactly
        const int4* p = (const int4*)(g_deg + tid * 20);
        #pragma unroll
        for (int i = 0; i < 5; i++) {
            v[i] = p[i];
            sum += v[i].x + v[i].y + v[i].z + v[i].w;
        }
    }
    int inc = sum;
    #pragma unroll
    for (int off = 1; off < 32; off <<= 1) {
        int u = __shfl_up_sync(0xffffffffu, inc, off);
        if (lane >= off) inc += u;
    }
    if (lane == 31) wsum[wid] = inc;
    __syncthreads();
    if (wid == 0) {
        int w = wsum[lane];
        #pragma unroll
        for (int off = 1; off < 32; off <<= 1) {
            int u = __shfl_up_sync(0xffffffffu, w, off);
            if (lane >= off) w += u;
        }
        wsum[lane] = w;
    }
    __syncthreads();
    int excl = inc - sum + (wid ? wsum[wid - 1] : 0);
    if (tid < 1000) {
        int run = excl;
        int base = tid * 20;
        int4* q = (int4*)(g_rowptr + base);
        #pragma unroll
        for (int i = 0; i < 5; i++) {
            int4 o;
            int n0 = base + i * 4;
            o.x = run; g_col[run] = n0;     g_cursor[n0]     = run + 1; run += v[i].x;
            o.y = run; g_col[run] = n0 + 1; g_cursor[n0 + 1] = run + 1; run += v[i].y;
            o.z = run; g_col[run] = n0 + 2; g_cursor[n0 + 2] = run + 1; run += v[i].z;
            o.w = run; g_col[run] = n0 + 3; g_cursor[n0 + 3] = run + 1; run += v[i].w;
            q[i] = o;
        }
    }
    if (tid == 0) g_rowptr[NN] = wsum[31];
}

__global__ void scatter_kernel(const int* __restrict__ ei) {
    int e = blockIdx.x * blockDim.x + threadIdx.x;
    if (e >= EE) return;
    int src = ei[e];
    int dst = ei[EE + e];
    int p = atomicAdd(&g_cursor[dst], 1);
    g_col[p] = src;
}

// ---------------- SGEMM (FFMA2, double-buffered, dup-B) ---------------------
// C[NN,256] = A[NN,K] @ B[K,256]; BM=128 BN=64(=one head) BK=16, 256 thr,
// micro 8(M)x4(N) per thread, M-pairs packed in f32x2. Fused concat + alpha.
__global__ void __launch_bounds__(256, 2)
sgemm_fused(const float* __restrict__ A, const float* __restrict__ x,
            const float* __restrict__ pos, const float* __restrict__ Bw,
            float* __restrict__ C, int K, int mode,
            const float* __restrict__ a_src, const float* __restrict__ a_dst) {
    __shared__ float As[2][16][132];    // [buf][k][m], padded
    __shared__ ull   Bs[2][16][64];     // [buf][k][n] duplicated {b,b}
    __shared__ float s_as[64], s_ad[64];

    int tid = threadIdx.x;
    int bm = blockIdx.x * 128;
    int hd = blockIdx.y;            // head index (BN == CC)
    int bn = hd * 64;

    if (tid < 64) { s_as[tid] = a_src[bn + tid]; s_ad[tid] = a_dst[bn + tid]; }

    int ty = tid >> 4, tx = tid & 15;
    int m0 = ty * 8, n0 = tx * 4;
    int ar = tid >> 2;              // 0..63
    int ac = (tid & 3) * 4;         // 0,4,8,12
    int br = tid >> 4;              // 0..15
    int bc = (tid & 15) * 4;        // 0..60 (ull index)

    int row0 = bm + ar, row1 = bm + ar + 64;
    const int T = K >> 4;

    ull acc[4][4];
    #pragma unroll
    for (int i = 0; i < 4; i++)
        #pragma unroll
        for (int j = 0; j < 4; j++) acc[i][j] = 0ull;

    float4 av0, av1, bv;

    // ---- A/B tile fetch into registers (k0 = tile index * 16) ----
    auto fetchA = [&](int k0, int row) -> float4 {
        float4 v = make_float4(0.f, 0.f, 0.f, 0.f);
        if (row < NN) {
            if (mode == 0) {
                v = *(const float4*)(A + (size_t)row * K + k0 + ac);
            } else {
                int c = k0 + ac;      // concat(pos[2], x[62])
                if (c == 0) {
                    float2 p = *(const float2*)(pos + (size_t)row * 2);
                    float2 q = *(const float2*)(x + (size_t)row * 62);
                    v = make_float4(p.x, p.y, q.x, q.y);
                } else {
                    float2 q0 = *(const float2*)(x + (size_t)row * 62 + c - 2);
                    float2 q1 = *(const float2*)(x + (size_t)row * 62 + c);
                    v = make_float4(q0.x, q0.y, q1.x, q1.y);
                }
            }
        }
        return v;
    };

    // prologue: tile 0
    av0 = fetchA(0, row0);
    av1 = fetchA(0, row1);
    bv  = *(const float4*)(Bw + (size_t)br * FH + bn + bc);
    {
        As[0][ac + 0][ar] = av0.x; As[0][ac + 1][ar] = av0.y;
        As[0][ac + 2][ar] = av0.z; As[0][ac + 3][ar] = av0.w;
        As[0][ac + 0][ar + 64] = av1.x; As[0][ac + 1][ar + 64] = av1.y;
        As[0][ac + 2][ar + 64] = av1.z; As[0][ac + 3][ar + 64] = av1.w;
        ulonglong2 d01, d23;
        d01.x = dup2(bv.x); d01.y = dup2(bv.y);
        d23.x = dup2(bv.z); d23.y = dup2(bv.w);
        *(ulonglong2*)&Bs[0][br][bc]     = d01;
        *(ulonglong2*)&Bs[0][br][bc + 2] = d23;
    }
    __syncthreads();

    for (int t = 0; t < T; t++) {
        int cur = t & 1;
        bool has_next = (t + 1 < T);
        if (has_next) {
            int k0 = (t + 1) << 4;
            av0 = fetchA(k0, row0);
            av1 = fetchA(k0, row1);
            bv  = *(const float4*)(Bw + (size_t)(k0 + br) * FH + bn + bc);
        }
        #pragma unroll
        for (int kk = 0; kk < 16; kk++) {
            ulonglong2 b01 = *(ulonglong2*)&Bs[cur][kk][n0];
            ulonglong2 b23 = *(ulonglong2*)&Bs[cur][kk][n0 + 2];
            ulonglong2 a01 = *(ulonglong2*)&As[cur][kk][m0];
            ulonglong2 a23 = *(ulonglong2*)&As[cur][kk][m0 + 4];
            ull aa[4] = {a01.x, a01.y, a23.x, a23.y};
            #pragma unroll
            for (int mi = 0; mi < 4; mi++) {
                fma2(acc[mi][0], aa[mi], b01.x);
                fma2(acc[mi][1], aa[mi], b01.y);
                fma2(acc[mi][2], aa[mi], b23.x);
                fma2(acc[mi][3], aa[mi], b23.y);
            }
        }
        if (has_next) {
            int nxt = 1 - cur;
            As[nxt][ac + 0][ar] = av0.x; As[nxt][ac + 1][ar] = av0.y;
            As[nxt][ac + 2][ar] = av0.z; As[nxt][ac + 3][ar] = av0.w;
            As[nxt][ac + 0][ar + 64] = av1.x; As[nxt][ac + 1][ar + 64] = av1.y;
            As[nxt][ac + 2][ar + 64] = av1.z; As[nxt][ac + 3][ar + 64] = av1.w;
            ulonglong2 d01, d23;
            d01.x = dup2(bv.x); d01.y = dup2(bv.y);
            d23.x = dup2(bv.z); d23.y = dup2(bv.w);
            *(ulonglong2*)&Bs[nxt][br][bc]     = d01;
            *(ulonglong2*)&Bs[nxt][br][bc + 2] = d23;
            __syncthreads();
        }
    }

    // ---- fused alpha dots ----
    ull ps[4] = {0,0,0,0}, pd[4] = {0,0,0,0};
    #pragma unroll
    for (int nj = 0; nj < 4; nj++) {
        ull w_s = dup2(s_as[n0 + nj]);
        ull w_d = dup2(s_ad[n0 + nj]);
        #pragma unroll
        for (int mi = 0; mi < 4; mi++) {
            fma2(ps[mi], acc[mi][nj], w_s);
            fma2(pd[mi], acc[mi][nj], w_d);
        }
    }
    #pragma unroll
    for (int s = 1; s < 16; s <<= 1) {
        #pragma unroll
        for (int mi = 0; mi < 4; mi++) {
            ps[mi] = add2(ps[mi], __shfl_xor_sync(0xffffffffu, ps[mi], s));
            pd[mi] = add2(pd[mi], __shfl_xor_sync(0xffffffffu, pd[mi], s));
        }
    }
    if (tx == 0) {
        #pragma unroll
        for (int mi = 0; mi < 4; mi++) {
            int row = bm + m0 + 2 * mi;
            float slo, shi, dlo, dhi;
            unpack2(ps[mi], slo, shi);
            unpack2(pd[mi], dlo, dhi);
            if (row < NN)     { g_as[row * HH + hd] = slo; g_ad[row * HH + hd] = dlo; }
            if (row + 1 < NN) { g_as[(row + 1) * HH + hd] = shi; g_ad[(row + 1) * HH + hd] = dhi; }
        }
    }

    // ---- C writes ----
    #pragma unroll
    for (int mi = 0; mi < 4; mi++) {
        int row = bm + m0 + 2 * mi;
        float lo0, hi0, lo1, hi1, lo2, hi2, lo3, hi3;
        unpack2(acc[mi][0], lo0, hi0);
        unpack2(acc[mi][1], lo1, hi1);
        unpack2(acc[mi][2], lo2, hi2);
        unpack2(acc[mi][3], lo3, hi3);
        if (row < NN)
            *(float4*)(C + (size_t)row * FH + bn + n0) = make_float4(lo0, lo1, lo2, lo3);
        if (row + 1 < NN)
            *(float4*)(C + (size_t)(row + 1) * FH + bn + n0) = make_float4(hi0, hi1, hi2, hi3);
    }
}

// ---------------- attention aggregation: one block per dst node -------------
__global__ void aggregate_kernel(const float* __restrict__ h, const float* __restrict__ bias,
                                 float* __restrict__ outp) {
    int n = blockIdx.x;
    int tid = threadIdx.x;                  // 128
    int start = g_rowptr[n], end = g_rowptr[n + 1];

    __shared__ float s_m[HH];
    __shared__ float s_rd[HH];
    __shared__ float s_alpha[32][HH];
    __shared__ int   s_src[32];

    const float4* as4 = (const float4*)g_as;
    float4 adv = ((const float4*)g_ad)[n];
    float adh[HH] = {adv.x, adv.y, adv.z, adv.w};

    if (tid < 32) {
        float m[HH] = {-1e30f, -1e30f, -1e30f, -1e30f};
        float d[HH] = {0.f, 0.f, 0.f, 0.f};
        for (int j = start + tid; j < end; j += 32) {
            int s = g_col[j];
            float4 av = as4[s];
            float ee[HH] = {av.x + adh[0], av.y + adh[1], av.z + adh[2], av.w + adh[3]};
            #pragma unroll
            for (int hd = 0; hd < HH; hd++) {
                float e = ee[hd];
                e = (e > 0.f) ? e : 0.2f * e;
                float nm = fmaxf(m[hd], e);
                d[hd] = d[hd] * __expf(m[hd] - nm) + __expf(e - nm);
                m[hd] = nm;
            }
        }
        #pragma unroll
        for (int off = 16; off > 0; off >>= 1) {
            #pragma unroll
            for (int hd = 0; hd < HH; hd++) {
                float om = __shfl_xor_sync(0xffffffffu, m[hd], off);
                float od = __shfl_xor_sync(0xffffffffu, d[hd], off);
                float nm = fmaxf(m[hd], om);
                d[hd] = d[hd] * __expf(m[hd] - nm) + od * __expf(om - nm);
                m[hd] = nm;
            }
        }
        if (tid < HH) {
            s_m[tid] = m[tid];
            s_rd[tid] = 1.f / (d[tid] + 1e-16f);
        }
    }
    __syncthreads();

    float accA0 = 0.f, accA1 = 0.f, accB0 = 0.f, accB1 = 0.f;
    int c0 = 2 * tid;
    int myh = tid >> 5;
    for (int base = start; base < end; base += 32) {
        int cnt = min(32, end - base);
        if (tid < cnt) {
            int s = g_col[base + tid];
            s_src[tid] = s;
            float4 av = as4[s];
            float ee[HH] = {av.x + adh[0], av.y + adh[1], av.z + adh[2], av.w + adh[3]};
            #pragma unroll
            for (int hd = 0; hd < HH; hd++) {
                float e = ee[hd];
                e = (e > 0.f) ? e : 0.2f * e;
                s_alpha[tid][hd] = __expf(e - s_m[hd]) * s_rd[hd];
            }
        }
        __syncthreads();
        int k = 0;
        for (; k + 2 <= cnt; k += 2) {
            int sA = s_src[k], sB = s_src[k + 1];
            float aA = s_alpha[k][myh], aB = s_alpha[k + 1][myh];
            float2 hA = *(const float2*)(h + (size_t)sA * FH + c0);
            float2 hB = *(const float2*)(h + (size_t)sB * FH + c0);
            accA0 = fmaf(hA.x, aA, accA0);
            accA1 = fmaf(hA.y, aA, accA1);
            accB0 = fmaf(hB.x, aB, accB0);
            accB1 = fmaf(hB.y, aB, accB1);
        }
        if (k < cnt) {
            int sA = s_src[k];
            float aA = s_alpha[k][myh];
            float2 hA = *(const float2*)(h + (size_t)sA * FH + c0);
            accA0 = fmaf(hA.x, aA, accA0);
            accA1 = fmaf(hA.y, aA, accA1);
        }
        __syncthreads();
    }
    outp[(size_t)n * FH + c0]     = accA0 + accB0 + bias[c0];
    outp[(size_t)n * FH + c0 + 1] = accA1 + accB1 + bias[c0 + 1];
}

// ---------------- pooling ---------------------------------------------------
__global__ void count_kernel(const int* __restrict__ batch) {
    __shared__ int s[256];
    int b = blockIdx.x, tid = threadIdx.x;
    int c = 0;
    for (int i = tid; i < NN; i += 256) c += (batch[i] == b);
    s[tid] = c;
    __syncthreads();
    for (int off = 128; off > 0; off >>= 1) {
        if (tid < off) s[tid] += s[tid + off];
        __syncthreads();
    }
    if (tid == 0) g_cnt[b] = s[0];
}

__global__ void pool_kernel(const float* __restrict__ outp, const int* __restrict__ batch) {
    int n0 = blockIdx.x * 64;
    int tid = threadIdx.x;                // 256 = channel
    int nend = min(n0 + 64, NN);
    float acc = 0.f;
    int cur = batch[n0];
    for (int n = n0; n < nend; n++) {
        int bb = batch[n];
        if (bb != cur) {
            atomicAdd(&g_pool[cur * FH + tid], acc);
            acc = 0.f; cur = bb;
        }
        acc += outp[(size_t)n * FH + tid];
    }
    atomicAdd(&g_pool[cur * FH + tid], acc);
}

// ---------------- MLP tail ---------------------------------------------------
__global__ void mlp_kernel(const float* __restrict__ lw1, const float* __restrict__ lb1,
                           const float* __restrict__ lw2, const float* __restrict__ lb2,
                           float* __restrict__ out) {
    __shared__ float s_in[FH];
    __shared__ float s_mid[128];
    int g = blockIdx.x, tid = threadIdx.x;   // 128 threads
    float inv = 1.f / fmaxf((float)g_cnt[g], 1.f);
    s_in[tid]       = g_pool[g * FH + tid] * inv;
    s_in[tid + 128] = g_pool[g * FH + tid + 128] * inv;
    __syncthreads();
    float acc = lb1[tid];
    #pragma unroll 8
    for (int k = 0; k < FH; k++) acc = fmaf(s_in[k], lw1[k * 128 + tid], acc);
    s_mid[tid] = fmaxf(acc, 0.f);
    __syncthreads();
    if (tid < 10) {
        float a = lb2[tid];
        #pragma unroll 8
        for (int k = 0; k < 128; k++) a = fmaf(s_mid[k], lw2[k * 10 + tid], a);
        out[g * 10 + tid] = fmaxf(a, 0.f);
    }
}

// ---------------- launch ------------------------------------------------------
extern "C" void kernel_launch(void* const* d_in, const int* in_sizes, int n_in,
                              void* d_out, int out_size) {
    const float* x     = (const float*)d_in[0];
    const float* pos   = (const float*)d_in[1];
    const int*   ei    = (const int*)d_in[2];
    const int*   batch = (const int*)d_in[3];
    const float* W1   = (const float*)d_in[4];
    const float* as1  = (const float*)d_in[5];
    const float* ad1  = (const float*)d_in[6];
    const float* b1   = (const float*)d_in[7];
    const float* W2   = (const float*)d_in[8];
    const float* as2  = (const float*)d_in[9];
    const float* ad2  = (const float*)d_in[10];
    const float* b2   = (const float*)d_in[11];
    const float* lw1  = (const float*)d_in[12];
    const float* lb1  = (const float*)d_in[13];
    const float* lw2  = (const float*)d_in[14];
    const float* lb2  = (const float*)d_in[15];
    float* out = (float*)d_out;

    float *p_b1, *p_b2;
    cudaGetSymbolAddress((void**)&p_b1, g_buf1);
    cudaGetSymbolAddress((void**)&p_b2, g_buf2);

    static cudaStream_t s1 = nullptr;
    static cudaEvent_t ev_fork = nullptr, ev_join = nullptr;
    if (!s1) {
        cudaStreamCreateWithFlags(&s1, cudaStreamNonBlocking);
        cudaEventCreateWithFlags(&ev_fork, cudaEventDisableTiming);
        cudaEventCreateWithFlags(&ev_join, cudaEventDisableTiming);
    }

    dim3 gg((NN + 127) / 128, HH);

    // fork side stream off the main (capture) stream
    cudaEventRecord(ev_fork, 0);
    cudaStreamWaitEvent(s1, ev_fork, 0);

    // main stream: CSR build            side stream: GEMM1 + count
    init_zero_kernel<<<(NN + 255) / 256, 256>>>();
    hist_kernel<<<(EE + 255) / 256, 256>>>(ei);
    scan_selfloop_kernel<<<1, 1024>>>();
    sgemm_fused<<<gg, 256, 0, s1>>>(nullptr, x, pos, W1, p_b1, 64, 1, as1, ad1);
    scatter_kernel<<<(EE + 255) / 256, 256>>>(ei);
    count_kernel<<<BG, 256, 0, s1>>>(batch);

    // join
    cudaEventRecord(ev_join, s1);
    cudaStreamWaitEvent(0, ev_join, 0);

    // ---- GAT layer 1 aggregation ----
    aggregate_kernel<<<NN, 128>>>(p_b1, b1, p_b2);

    // ---- GAT layer 2 ----
    sgemm_fused<<<gg, 256>>>(p_b2, x, pos, W2, p_b1, 256, 0, as2, ad2);
    aggregate_kernel<<<NN, 128>>>(p_b1, b2, p_b2);

    // ---- pool + MLP ----
    pool_kernel<<<(NN + 63) / 64, 256>>>(p_b2, batch);
    mlp_kernel<<<BG, 128>>>(lw1, lb1, lw2, lb2, out);
}

// round 6
// speedup vs baseline: 1.1873x; 1.1873x over previous
#include <cuda_runtime.h>
#include <math.h>

#define NN 20000
#define EE 320000
#define ET 340000   // EE + NN self loops
#define BG 32
#define FH 256      // H*C
#define HH 4
#define CC 64

typedef unsigned long long ull;

// ---------------- packed f32x2 helpers (FFMA2 — 2x fp32 FMA throughput) -----
__device__ __forceinline__ void fma2(ull &d, ull a, ull b) {
    asm("fma.rn.f32x2 %0, %1, %2, %0;" : "+l"(d) : "l"(a), "l"(b));
}
__device__ __forceinline__ ull add2(ull a, ull b) {
    ull r; asm("add.rn.f32x2 %0, %1, %2;" : "=l"(r) : "l"(a), "l"(b)); return r;
}
__device__ __forceinline__ ull dup2(float x) {
    ull r; asm("mov.b64 %0, {%1, %1};" : "=l"(r) : "f"(x)); return r;
}
__device__ __forceinline__ void unpack2(ull v, float &lo, float &hi) {
    asm("mov.b64 {%0, %1}, %2;" : "=f"(lo), "=f"(hi) : "l"(v));
}

// ---------------- scratch (device globals; no allocation allowed) ----------
__device__ __align__(16) float g_buf1[NN * FH];   // GEMM output (h)
__device__ __align__(16) float g_buf2[NN * FH];   // aggregation output
__device__ __align__(16) float g_as[NN * HH];
__device__ __align__(16) float g_ad[NN * HH];
__device__ __align__(16) int   g_deg[NN];
__device__ __align__(16) int   g_rowptr[NN + 1];
__device__ int   g_cursor[NN];
__device__ int   g_col[ET];
__device__ float g_pool[BG * FH];
__device__ int   g_cnt[BG];

// ---------------- init: deg=1 (self loop), zero pool/cnt --------------------
__global__ void init_zero_kernel() {
    int n = blockIdx.x * blockDim.x + threadIdx.x;
    if (n < NN) g_deg[n] = 1;
    if (n < BG * FH) g_pool[n] = 0.f;
    if (n < BG) g_cnt[n] = 0;
}

__global__ void hist_kernel(const int* __restrict__ ei) {
    int e = blockIdx.x * blockDim.x + threadIdx.x;
    if (e >= EE) return;
    int dst = ei[EE + e];
    atomicAdd(&g_deg[dst], 1);
}

// exclusive scan over g_deg + fused self-loop/cursor init, single block
__global__ void scan_selfloop_kernel() {
    __shared__ int wsum[32];
    int tid = threadIdx.x;
    int lane = tid & 31, wid = tid >> 5;
    int4 v[5];
    int sum = 0;
    if (tid < 1000) {               // 1000 * 20 = 20000 exactly
        const int4* p = (const int4*)(g_deg + tid * 20);
        #pragma unroll
        for (int i = 0; i < 5; i++) {
            v[i] = p[i];
            sum += v[i].x + v[i].y + v[i].z + v[i].w;
        }
    }
    int inc = sum;
    #pragma unroll
    for (int off = 1; off < 32; off <<= 1) {
        int u = __shfl_up_sync(0xffffffffu, inc, off);
        if (lane >= off) inc += u;
    }
    if (lane == 31) wsum[wid] = inc;
    __syncthreads();
    if (wid == 0) {
        int w = wsum[lane];
        #pragma unroll
        for (int off = 1; off < 32; off <<= 1) {
            int u = __shfl_up_sync(0xffffffffu, w, off);
            if (lane >= off) w += u;
        }
        wsum[lane] = w;
    }
    __syncthreads();
    int excl = inc - sum + (wid ? wsum[wid - 1] : 0);
    if (tid < 1000) {
        int run = excl;
        int base = tid * 20;
        int4* q = (int4*)(g_rowptr + base);
        #pragma unroll
        for (int i = 0; i < 5; i++) {
            int4 o;
            int n0 = base + i * 4;
            o.x = run; g_col[run] = n0;     g_cursor[n0]     = run + 1; run += v[i].x;
            o.y = run; g_col[run] = n0 + 1; g_cursor[n0 + 1] = run + 1; run += v[i].y;
            o.z = run; g_col[run] = n0 + 2; g_cursor[n0 + 2] = run + 1; run += v[i].z;
            o.w = run; g_col[run] = n0 + 3; g_cursor[n0 + 3] = run + 1; run += v[i].w;
            q[i] = o;
        }
    }
    if (tid == 0) g_rowptr[NN] = wsum[31];
}

__global__ void scatter_kernel(const int* __restrict__ ei) {
    int e = blockIdx.x * blockDim.x + threadIdx.x;
    if (e >= EE) return;
    int src = ei[e];
    int dst = ei[EE + e];
    int p = atomicAdd(&g_cursor[dst], 1);
    g_col[p] = src;
}

// ---------------- SGEMM (FFMA2) BM=128 BN=128 BK=16, micro 8x8 --------------
// C[NN,256] = A[NN,K] @ B[K,256]; blockIdx.y selects 128-col half (2 heads).
// Fused concat (layer 1) + fused alpha_src/alpha_dst dots per head.
__global__ void __launch_bounds__(256, 2)
sgemm_fused(const float* __restrict__ A, const float* __restrict__ x,
            const float* __restrict__ pos, const float* __restrict__ Bw,
            float* __restrict__ C, int K, int mode,
            const float* __restrict__ a_src, const float* __restrict__ a_dst) {
    __shared__ float As[16][132];   // [k][m], padded
    __shared__ float Bs[16][128];   // [k][n]
    __shared__ float s_as[128], s_ad[128];

    int tid = threadIdx.x;
    int bm = blockIdx.x * 128;
    int bn = blockIdx.y * 128;      // two heads per block

    if (tid < 128) { s_as[tid] = a_src[bn + tid]; s_ad[tid] = a_dst[bn + tid]; }

    int ty = tid >> 4, tx = tid & 15;
    int m0 = ty * 8, n0 = tx * 8;
    int ar = tid >> 2;              // 0..63
    int ac = (tid & 3) * 4;         // 0,4,8,12
    int br = tid >> 4;              // 0..15 (k row of B tile)
    int bc = (tid & 15) * 8;        // 0..120

    int row0 = bm + ar, row1 = bm + ar + 64;

    ull acc[4][8];
    #pragma unroll
    for (int i = 0; i < 4; i++)
        #pragma unroll
        for (int j = 0; j < 8; j++) acc[i][j] = 0ull;

    for (int k0 = 0; k0 < K; k0 += 16) {
        // A tile: 128 rows x 16 k (two row-halves per thread)
        #pragma unroll
        for (int half = 0; half < 2; half++) {
            int r = ar + half * 64;
            int row = half ? row1 : row0;
            float4 v = make_float4(0.f, 0.f, 0.f, 0.f);
            if (row < NN) {
                if (mode == 0) {
                    v = *(const float4*)(A + (size_t)row * K + k0 + ac);
                } else {
                    int c = k0 + ac;      // concat(pos[2], x[62])
                    if (c == 0) {
                        float2 p = *(const float2*)(pos + (size_t)row * 2);
                        float2 q = *(const float2*)(x + (size_t)row * 62);
                        v = make_float4(p.x, p.y, q.x, q.y);
                    } else {
                        float2 q0 = *(const float2*)(x + (size_t)row * 62 + c - 2);
                        float2 q1 = *(const float2*)(x + (size_t)row * 62 + c);
                        v = make_float4(q0.x, q0.y, q1.x, q1.y);
                    }
                }
            }
            As[ac + 0][r] = v.x; As[ac + 1][r] = v.y;
            As[ac + 2][r] = v.z; As[ac + 3][r] = v.w;
        }
        // B tile: 16 k x 128 n (two float4 per thread)
        const float* bp = Bw + (size_t)(k0 + br) * FH + bn + bc;
        *(float4*)&Bs[br][bc]     = *(const float4*)bp;
        *(float4*)&Bs[br][bc + 4] = *(const float4*)(bp + 4);
        __syncthreads();
        #pragma unroll
        for (int kk = 0; kk < 16; kk++) {
            ulonglong2 a01 = *(ulonglong2*)&As[kk][m0];
            ulonglong2 a23 = *(ulonglong2*)&As[kk][m0 + 4];
            float4 b0 = *(float4*)&Bs[kk][n0];
            float4 b1 = *(float4*)&Bs[kk][n0 + 4];
            ull aa[4] = {a01.x, a01.y, a23.x, a23.y};
            ull bb[8] = {dup2(b0.x), dup2(b0.y), dup2(b0.z), dup2(b0.w),
                         dup2(b1.x), dup2(b1.y), dup2(b1.z), dup2(b1.w)};
            #pragma unroll
            for (int mi = 0; mi < 4; mi++)
                #pragma unroll
                for (int nj = 0; nj < 8; nj++)
                    fma2(acc[mi][nj], aa[mi], bb[nj]);
        }
        __syncthreads();
    }

    // ---- fused alpha dots: this thread's 8 cols live in one head ----
    ull ps[4] = {0,0,0,0}, pd[4] = {0,0,0,0};
    #pragma unroll
    for (int nj = 0; nj < 8; nj++) {
        ull w_s = dup2(s_as[n0 + nj]);
        ull w_d = dup2(s_ad[n0 + nj]);
        #pragma unroll
        for (int mi = 0; mi < 4; mi++) {
            fma2(ps[mi], acc[mi][nj], w_s);
            fma2(pd[mi], acc[mi][nj], w_d);
        }
    }
    // reduce over the 8 lanes sharing a head (lane bits 0..2 of tx)
    #pragma unroll
    for (int s = 1; s < 8; s <<= 1) {
        #pragma unroll
        for (int mi = 0; mi < 4; mi++) {
            ps[mi] = add2(ps[mi], __shfl_xor_sync(0xffffffffu, ps[mi], s));
            pd[mi] = add2(pd[mi], __shfl_xor_sync(0xffffffffu, pd[mi], s));
        }
    }
    if ((tx & 7) == 0) {
        int hd = blockIdx.y * 2 + (tx >> 3);
        #pragma unroll
        for (int mi = 0; mi < 4; mi++) {
            int row = bm + m0 + 2 * mi;
            float slo, shi, dlo, dhi;
            unpack2(ps[mi], slo, shi);
            unpack2(pd[mi], dlo, dhi);
            if (row < NN)     { g_as[row * HH + hd] = slo; g_ad[row * HH + hd] = dlo; }
            if (row + 1 < NN) { g_as[(row + 1) * HH + hd] = shi; g_ad[(row + 1) * HH + hd] = dhi; }
        }
    }

    // ---- C writes ----
    #pragma unroll
    for (int mi = 0; mi < 4; mi++) {
        int row = bm + m0 + 2 * mi;
        float lo[8], hi[8];
        #pragma unroll
        for (int nj = 0; nj < 8; nj++) unpack2(acc[mi][nj], lo[nj], hi[nj]);
        if (row < NN) {
            *(float4*)(C + (size_t)row * FH + bn + n0)     = make_float4(lo[0], lo[1], lo[2], lo[3]);
            *(float4*)(C + (size_t)row * FH + bn + n0 + 4) = make_float4(lo[4], lo[5], lo[6], lo[7]);
        }
        if (row + 1 < NN) {
            *(float4*)(C + (size_t)(row + 1) * FH + bn + n0)     = make_float4(hi[0], hi[1], hi[2], hi[3]);
            *(float4*)(C + (size_t)(row + 1) * FH + bn + n0 + 4) = make_float4(hi[4], hi[5], hi[6], hi[7]);
        }
    }
}

// ---------------- attention aggregation: one block per dst node -------------
__global__ void aggregate_kernel(const float* __restrict__ h, const float* __restrict__ bias,
                                 float* __restrict__ outp) {
    int n = blockIdx.x;
    int tid = threadIdx.x;                  // 128
    int start = g_rowptr[n], end = g_rowptr[n + 1];

    __shared__ float s_m[HH];
    __shared__ float s_rd[HH];
    __shared__ float s_alpha[32][HH];
    __shared__ int   s_src[32];

    const float4* as4 = (const float4*)g_as;
    float4 adv = ((const float4*)g_ad)[n];
    float adh[HH] = {adv.x, adv.y, adv.z, adv.w};

    if (tid < 32) {
        float m[HH] = {-1e30f, -1e30f, -1e30f, -1e30f};
        float d[HH] = {0.f, 0.f, 0.f, 0.f};
        for (int j = start + tid; j < end; j += 32) {
            int s = g_col[j];
            float4 av = as4[s];
            float ee[HH] = {av.x + adh[0], av.y + adh[1], av.z + adh[2], av.w + adh[3]};
            #pragma unroll
            for (int hd = 0; hd < HH; hd++) {
                float e = ee[hd];
                e = (e > 0.f) ? e : 0.2f * e;
                float nm = fmaxf(m[hd], e);
                d[hd] = d[hd] * __expf(m[hd] - nm) + __expf(e - nm);
                m[hd] = nm;
            }
        }
        #pragma unroll
        for (int off = 16; off > 0; off >>= 1) {
            #pragma unroll
            for (int hd = 0; hd < HH; hd++) {
                float om = __shfl_xor_sync(0xffffffffu, m[hd], off);
                float od = __shfl_xor_sync(0xffffffffu, d[hd], off);
                float nm = fmaxf(m[hd], om);
                d[hd] = d[hd] * __expf(m[hd] - nm) + od * __expf(om - nm);
                m[hd] = nm;
            }
        }
        if (tid < HH) {
            s_m[tid] = m[tid];
            s_rd[tid] = 1.f / (d[tid] + 1e-16f);
        }
    }
    __syncthreads();

    float accA0 = 0.f, accA1 = 0.f, accB0 = 0.f, accB1 = 0.f;
    int c0 = 2 * tid;
    int myh = tid >> 5;
    for (int base = start; base < end; base += 32) {
        int cnt = min(32, end - base);
        if (tid < cnt) {
            int s = g_col[base + tid];
            s_src[tid] = s;
            float4 av = as4[s];
            float ee[HH] = {av.x + adh[0], av.y + adh[1], av.z + adh[2], av.w + adh[3]};
            #pragma unroll
            for (int hd = 0; hd < HH; hd++) {
                float e = ee[hd];
                e = (e > 0.f) ? e : 0.2f * e;
                s_alpha[tid][hd] = __expf(e - s_m[hd]) * s_rd[hd];
            }
        }
        __syncthreads();
        int k = 0;
        for (; k + 2 <= cnt; k += 2) {
            int sA = s_src[k], sB = s_src[k + 1];
            float aA = s_alpha[k][myh], aB = s_alpha[k + 1][myh];
            float2 hA = *(const float2*)(h + (size_t)sA * FH + c0);
            float2 hB = *(const float2*)(h + (size_t)sB * FH + c0);
            accA0 = fmaf(hA.x, aA, accA0);
            accA1 = fmaf(hA.y, aA, accA1);
            accB0 = fmaf(hB.x, aB, accB0);
            accB1 = fmaf(hB.y, aB, accB1);
        }
        if (k < cnt) {
            int sA = s_src[k];
            float aA = s_alpha[k][myh];
            float2 hA = *(const float2*)(h + (size_t)sA * FH + c0);
            accA0 = fmaf(hA.x, aA, accA0);
            accA1 = fmaf(hA.y, aA, accA1);
        }
        __syncthreads();
    }
    outp[(size_t)n * FH + c0]     = accA0 + accB0 + bias[c0];
    outp[(size_t)n * FH + c0 + 1] = accA1 + accB1 + bias[c0 + 1];
}

// ---------------- pooling ---------------------------------------------------
__global__ void count_kernel(const int* __restrict__ batch) {
    __shared__ int s[256];
    int b = blockIdx.x, tid = threadIdx.x;
    int c = 0;
    for (int i = tid; i < NN; i += 256) c += (batch[i] == b);
    s[tid] = c;
    __syncthreads();
    for (int off = 128; off > 0; off >>= 1) {
        if (tid < off) s[tid] += s[tid + off];
        __syncthreads();
    }
    if (tid == 0) g_cnt[b] = s[0];
}

__global__ void pool_kernel(const float* __restrict__ outp, const int* __restrict__ batch) {
    int n0 = blockIdx.x * 64;
    int tid = threadIdx.x;                // 256 = channel
    int nend = min(n0 + 64, NN);
    float acc = 0.f;
    int cur = batch[n0];
    for (int n = n0; n < nend; n++) {
        int bb = batch[n];
        if (bb != cur) {
            atomicAdd(&g_pool[cur * FH + tid], acc);
            acc = 0.f; cur = bb;
        }
        acc += outp[(size_t)n * FH + tid];
    }
    atomicAdd(&g_pool[cur * FH + tid], acc);
}

// ---------------- MLP tail ---------------------------------------------------
__global__ void mlp_kernel(const float* __restrict__ lw1, const float* __restrict__ lb1,
                           const float* __restrict__ lw2, const float* __restrict__ lb2,
                           float* __restrict__ out) {
    __shared__ float s_in[FH];
    __shared__ float s_mid[128];
    int g = blockIdx.x, tid = threadIdx.x;   // 128 threads
    float inv = 1.f / fmaxf((float)g_cnt[g], 1.f);
    s_in[tid]       = g_pool[g * FH + tid] * inv;
    s_in[tid + 128] = g_pool[g * FH + tid + 128] * inv;
    __syncthreads();
    float acc = lb1[tid];
    #pragma unroll 8
    for (int k = 0; k < FH; k++) acc = fmaf(s_in[k], lw1[k * 128 + tid], acc);
    s_mid[tid] = fmaxf(acc, 0.f);
    __syncthreads();
    if (tid < 10) {
        float a = lb2[tid];
        #pragma unroll 8
        for (int k = 0; k < 128; k++) a = fmaf(s_mid[k], lw2[k * 10 + tid], a);
        out[g * 10 + tid] = fmaxf(a, 0.f);
    }
}

// ---------------- launch ------------------------------------------------------
extern "C" void kernel_launch(void* const* d_in, const int* in_sizes, int n_in,
                              void* d_out, int out_size) {
    const float* x     = (const float*)d_in[0];
    const float* pos   = (const float*)d_in[1];
    const int*   ei    = (const int*)d_in[2];
    const int*   batch = (const int*)d_in[3];
    const float* W1   = (const float*)d_in[4];
    const float* as1  = (const float*)d_in[5];
    const float* ad1  = (const float*)d_in[6];
    const float* b1   = (const float*)d_in[7];
    const float* W2   = (const float*)d_in[8];
    const float* as2  = (const float*)d_in[9];
    const float* ad2  = (const float*)d_in[10];
    const float* b2   = (const float*)d_in[11];
    const float* lw1  = (const float*)d_in[12];
    const float* lb1  = (const float*)d_in[13];
    const float* lw2  = (const float*)d_in[14];
    const float* lb2  = (const float*)d_in[15];
    float* out = (float*)d_out;

    float *p_b1, *p_b2;
    cudaGetSymbolAddress((void**)&p_b1, g_buf1);
    cudaGetSymbolAddress((void**)&p_b2, g_buf2);

    static cudaStream_t s1 = nullptr;
    static cudaEvent_t ev_fork = nullptr, ev_join = nullptr;
    if (!s1) {
        cudaStreamCreateWithFlags(&s1, cudaStreamNonBlocking);
        cudaEventCreateWithFlags(&ev_fork, cudaEventDisableTiming);
        cudaEventCreateWithFlags(&ev_join, cudaEventDisableTiming);
    }

    dim3 gg((NN + 127) / 128, 2);   // 128-col halves (2 heads each)

    // fork side stream off the main (capture) stream
    cudaEventRecord(ev_fork, 0);
    cudaStreamWaitEvent(s1, ev_fork, 0);

    // main stream: CSR build            side stream: GEMM1 + count
    init_zero_kernel<<<(NN + 255) / 256, 256>>>();
    hist_kernel<<<(EE + 255) / 256, 256>>>(ei);
    scan_selfloop_kernel<<<1, 1024>>>();
    sgemm_fused<<<gg, 256, 0, s1>>>(nullptr, x, pos, W1, p_b1, 64, 1, as1, ad1);
    scatter_kernel<<<(EE + 255) / 256, 256>>>(ei);
    count_kernel<<<BG, 256, 0, s1>>>(batch);

    // join
    cudaEventRecord(ev_join, s1);
    cudaStreamWaitEvent(0, ev_join, 0);

    // ---- GAT layer 1 aggregation ----
    aggregate_kernel<<<NN, 128>>>(p_b1, b1, p_b2);

    // ---- GAT layer 2 ----
    sgemm_fused<<<gg, 256>>>(p_b2, x, pos, W2, p_b1, 256, 0, as2, ad2);
    aggregate_kernel<<<NN, 128>>>(p_b1, b2, p_b2);

    // ---- pool + MLP ----
    pool_kernel<<<(NN + 63) / 64, 256>>>(p_b2, batch);
    mlp_kernel<<<BG, 128>>>(lw1, lb1, lw2, lb2, out);
}

// round 8
// speedup vs baseline: 1.5196x; 1.2799x over previous
#include <cuda_runtime.h>
#include <cuda_bf16.h>
#include <math.h>

#define NN 20000
#define EE 320000
#define ET 340000   // EE + NN self loops
#define BG 32
#define FH 256      // H*C
#define HH 4
#define CC 64
#define NM16 1256   // ceil(20000/16) rounded to 157*8

// ---------------- scratch (device globals; no allocation allowed) ----------
__device__ __align__(16) float g_buf1[NN * FH];   // GEMM output (h)
__device__ __align__(16) float g_buf2[NN * FH];   // aggregation output
__device__ __align__(16) float g_as[NN * HH];
__device__ __align__(16) float g_ad[NN * HH];
__device__ __align__(16) int   g_deg[NN];
__device__ __align__(16) int   g_rowptr[NN + 1];
__device__ int   g_cursor[NN];
__device__ int   g_col[ET];
__device__ float g_pool[BG * FH];
__device__ int   g_cnt[BG];
// pre-packed mma fragments (m16n8k16 register layout), hi/lo split-bf16
__device__ __align__(16) unsigned g_af1[NM16 * 4 * 32 * 8];    // A layer1, K=64  (4 k16)
__device__ __align__(16) unsigned g_af2[NM16 * 16 * 32 * 8];   // A layer2, K=256 (16 k16)
__device__ __align__(16) unsigned g_bf1[32 * 4 * 32 * 4];      // B=W1^T frags
__device__ __align__(16) unsigned g_bf2[32 * 16 * 32 * 4];     // B=W2^T frags

// ---------------- fragment index helpers ------------------------------------
// A frag (m16n8k16 row): lane l holds row l/4 (+8), k pair 2(l%4) (+1), k+8.
// Layout: [a0h a1h a2h a3h a0l a1l a2l a3l] per (m16, k16, lane).
__device__ __forceinline__ int afrag_idx(int row, int p, int nk16) {
    int m16 = row >> 4, k16 = p >> 3;
    int lane = 4 * (row & 7) + (p & 3);
    int reg  = ((row >> 3) & 1) + 2 * ((p >> 2) & 1);
    return (((m16 * nk16) + k16) * 32 + lane) * 8 + reg;   // hi; lo at +4
}
// B frag (col): lane l holds n = l/4, k pair 2(l%4) (+1), and +8.
// Layout: [b0h b1h b0l b1l] per (n8, k16, lane).
__device__ __forceinline__ int bfrag_idx(int n, int p, int nk16) {
    int nt = n >> 3, k16 = p >> 3;
    int lane = 4 * (n & 7) + (p & 3);
    int reg = (p >> 2) & 1;
    return ((nt * nk16 + k16) * 32 + lane) * 4 + reg;      // hi; lo at +2
}
__device__ __forceinline__ void split2(float v0, float v1, unsigned &hi, unsigned &lo) {
    __nv_bfloat16 h0 = __float2bfloat16(v0), h1 = __float2bfloat16(v1);
    __nv_bfloat16 l0 = __float2bfloat16(v0 - __bfloat162float(h0));
    __nv_bfloat16 l1 = __float2bfloat16(v1 - __bfloat162float(h1));
    __nv_bfloat162 hh; hh.x = h0; hh.y = h1;
    __nv_bfloat162 ll; ll.x = l0; ll.y = l1;
    hi = *(unsigned*)&hh;
    lo = *(unsigned*)&ll;
}
__device__ __forceinline__ void mma16816(float* d, unsigned a0, unsigned a1, unsigned a2,
                                         unsigned a3, unsigned b0, unsigned b1) {
    asm volatile("mma.sync.aligned.m16n8k16.row.col.f32.bf16.bf16.f32 "
        "{%0,%1,%2,%3}, {%4,%5,%6,%7}, {%8,%9}, {%0,%1,%2,%3};"
        : "+f"(d[0]), "+f"(d[1]), "+f"(d[2]), "+f"(d[3])
        : "r"(a0), "r"(a1), "r"(a2), "r"(a3), "r"(b0), "r"(b1));
}

// ---------------- init / CSR build -----------------------------------------
__global__ void init_zero_kernel() {
    int n = blockIdx.x * blockDim.x + threadIdx.x;
    if (n < NN) g_deg[n] = 1;
    if (n < BG * FH) g_pool[n] = 0.f;
    if (n < BG) g_cnt[n] = 0;
}

__global__ void hist_kernel(const int* __restrict__ ei) {
    int e = blockIdx.x * blockDim.x + threadIdx.x;
    if (e >= EE) return;
    atomicAdd(&g_deg[ei[EE + e]], 1);
}

__global__ void scan_selfloop_kernel() {
    __shared__ int wsum[32];
    int tid = threadIdx.x;
    int lane = tid & 31, wid = tid >> 5;
    int4 v[5];
    int sum = 0;
    if (tid < 1000) {
        const int4* p = (const int4*)(g_deg + tid * 20);
        #pragma unroll
        for (int i = 0; i < 5; i++) { v[i] = p[i]; sum += v[i].x + v[i].y + v[i].z + v[i].w; }
    }
    int inc = sum;
    #pragma unroll
    for (int off = 1; off < 32; off <<= 1) {
        int u = __shfl_up_sync(0xffffffffu, inc, off);
        if (lane >= off) inc += u;
    }
    if (lane == 31) wsum[wid] = inc;
    __syncthreads();
    if (wid == 0) {
        int w = wsum[lane];
        #pragma unroll
        for (int off = 1; off < 32; off <<= 1) {
            int u = __shfl_up_sync(0xffffffffu, w, off);
            if (lane >= off) w += u;
        }
        wsum[lane] = w;
    }
    __syncthreads();
    int excl = inc - sum + (wid ? wsum[wid - 1] : 0);
    if (tid < 1000) {
        int run = excl;
        int base = tid * 20;
        int4* q = (int4*)(g_rowptr + base);
        #pragma unroll
        for (int i = 0; i < 5; i++) {
            int4 o;
            int n0 = base + i * 4;
            o.x = run; g_col[run] = n0;     g_cursor[n0]     = run + 1; run += v[i].x;
            o.y = run; g_col[run] = n0 + 1; g_cursor[n0 + 1] = run + 1; run += v[i].y;
            o.z = run; g_col[run] = n0 + 2; g_cursor[n0 + 2] = run + 1; run += v[i].z;
            o.w = run; g_col[run] = n0 + 3; g_cursor[n0 + 3] = run + 1; run += v[i].w;
            q[i] = o;
        }
    }
    if (tid == 0) g_rowptr[NN] = wsum[31];
}

__global__ void scatter_kernel(const int* __restrict__ ei) {
    int e = blockIdx.x * blockDim.x + threadIdx.x;
    if (e >= EE) return;
    int src = ei[e];
    int dst = ei[EE + e];
    int p = atomicAdd(&g_cursor[dst], 1);
    g_col[p] = src;
}

// ---------------- fragment packers ------------------------------------------
// layer-1 A = concat(pos, x): rows NN, K=64 (32 k-pairs)
__global__ void convert_x1_frag(const float* __restrict__ x, const float* __restrict__ pos) {
    int idx = blockIdx.x * blockDim.x + threadIdx.x;
    if (idx >= NN * 32) return;
    int row = idx >> 5, p = idx & 31;
    int k = 2 * p;
    float v0 = (k == 0) ? pos[row * 2]     : x[(size_t)row * 62 + k - 2];
    float v1 = (k == 0) ? pos[row * 2 + 1] : x[(size_t)row * 62 + k - 1];
    unsigned hi, lo;
    split2(v0, v1, hi, lo);
    int base = afrag_idx(row, p, 4);
    g_af1[base] = hi;
    g_af1[base + 4] = lo;
}

// B = W^T: W stored [K][256] row-major; pack frags for n in 0..255, kpairs 0..K/2
__global__ void convert_w_frag(const float* __restrict__ W, int np, int nk16,
                               unsigned* __restrict__ out) {
    int idx = blockIdx.x * blockDim.x + threadIdx.x;
    if (idx >= FH * np) return;
    int n = idx / np, p = idx - n * np;
    float v0 = W[(size_t)(2 * p) * FH + n];
    float v1 = W[(size_t)(2 * p + 1) * FH + n];
    unsigned hi, lo;
    split2(v0, v1, hi, lo);
    int base = bfrag_idx(n, p, nk16);
    out[base] = hi;
    out[base + 2] = lo;
}

// ---------------- mma.sync split-bf16 GEMM + fused alpha dots ----------------
// C[NN,256] = A @ B^T. 256 thr = 8 warps (4m x 2n), block tile 128x128.
__global__ void __launch_bounds__(256)
mma_gemm(const unsigned* __restrict__ Af, const unsigned* __restrict__ Bf,
         float* __restrict__ C, int nk16,
         const float* __restrict__ a_src, const float* __restrict__ a_dst) {
    __shared__ float s_as[128], s_ad[128];
    int tid = threadIdx.x, lane = tid & 31, w = tid >> 5;
    int bm = blockIdx.x * 128, bn = blockIdx.y * 128;
    int wm = w & 3, wn = w >> 2;
    if (tid < 128) { s_as[tid] = a_src[bn + tid]; s_ad[tid] = a_dst[bn + tid]; }
    __syncthreads();

    int mt0 = (bm >> 4) + wm * 2;        // global m16 tile (and +1)
    int nt0 = (bn >> 3) + wn * 8;        // global n8 tile of first col

    float acc[2][8][4];
    #pragma unroll
    for (int i = 0; i < 2; i++)
        #pragma unroll
        for (int j = 0; j < 8; j++)
            #pragma unroll
            for (int r = 0; r < 4; r++) acc[i][j][r] = 0.f;

    for (int k16 = 0; k16 < nk16; k16++) {
        const uint4* pa0 = (const uint4*)(Af + ((size_t)(mt0 * nk16 + k16) * 32 + lane) * 8);
        const uint4* pa1 = (const uint4*)(Af + ((size_t)((mt0 + 1) * nk16 + k16) * 32 + lane) * 8);
        uint4 ah0 = pa0[0], al0 = pa0[1];
        uint4 ah1 = pa1[0], al1 = pa1[1];
        #pragma unroll
        for (int nt = 0; nt < 8; nt++) {
            uint4 b = *(const uint4*)(Bf + ((size_t)((nt0 + nt) * nk16 + k16) * 32 + lane) * 4);
            mma16816(acc[0][nt], ah0.x, ah0.y, ah0.z, ah0.w, b.x, b.y);
            mma16816(acc[0][nt], al0.x, al0.y, al0.z, al0.w, b.x, b.y);
            mma16816(acc[0][nt], ah0.x, ah0.y, ah0.z, ah0.w, b.z, b.w);
            mma16816(acc[1][nt], ah1.x, ah1.y, ah1.z, ah1.w, b.x, b.y);
            mma16816(acc[1][nt], al1.x, al1.y, al1.z, al1.w, b.x, b.y);
            mma16816(acc[1][nt], ah1.x, ah1.y, ah1.z, ah1.w, b.z, b.w);
        }
    }

    // epilogue: C writes + per-head alpha dots (warp n-tile == one head)
    int q = lane >> 2, c2 = (lane & 3) * 2;
    int head = (bn + wn * 64) >> 6;
    #pragma unroll
    for (int mi = 0; mi < 2; mi++) {
        int r0 = bm + wm * 32 + mi * 16 + q;
        int r1 = r0 + 8;
        float ps0 = 0.f, pd0 = 0.f, ps1 = 0.f, pd1 = 0.f;
        #pragma unroll
        for (int nt = 0; nt < 8; nt++) {
            int nl = wn * 64 + nt * 8 + c2;
            float as0 = s_as[nl], as1 = s_as[nl + 1];
            float ad0 = s_ad[nl], ad1 = s_ad[nl + 1];
            ps0 += acc[mi][nt][0] * as0 + acc[mi][nt][1] * as1;
            pd0 += acc[mi][nt][0] * ad0 + acc[mi][nt][1] * ad1;
            ps1 += acc[mi][nt][2] * as0 + acc[mi][nt][3] * as1;
            pd1 += acc[mi][nt][2] * ad0 + acc[mi][nt][3] * ad1;
        }
        #pragma unroll
        for (int s = 1; s < 4; s <<= 1) {
            ps0 += __shfl_xor_sync(0xffffffffu, ps0, s);
            pd0 += __shfl_xor_sync(0xffffffffu, pd0, s);
            ps1 += __shfl_xor_sync(0xffffffffu, ps1, s);
            pd1 += __shfl_xor_sync(0xffffffffu, pd1, s);
        }
        if ((lane & 3) == 0) {
            if (r0 < NN) { g_as[r0 * HH + head] = ps0; g_ad[r0 * HH + head] = pd0; }
            if (r1 < NN) { g_as[r1 * HH + head] = ps1; g_ad[r1 * HH + head] = pd1; }
        }
        if (r0 < NN) {
            float* cp = C + (size_t)r0 * FH + bn + wn * 64 + c2;
            #pragma unroll
            for (int nt = 0; nt < 8; nt++)
                *(float2*)(cp + nt * 8) = make_float2(acc[mi][nt][0], acc[mi][nt][1]);
        }
        if (r1 < NN) {
            float* cp = C + (size_t)r1 * FH + bn + wn * 64 + c2;
            #pragma unroll
            for (int nt = 0; nt < 8; nt++)
                *(float2*)(cp + nt * 8) = make_float2(acc[mi][nt][2], acc[mi][nt][3]);
        }
    }
}

// ---------------- attention aggregation: one block per dst node -------------
// warp 0: online softmax stats; 128 threads: weighted gather (2 ch/thread).
// emit!=0: also pack layer-2 A fragments (hi/lo split).
__global__ void aggregate_kernel(const float* __restrict__ h, const float* __restrict__ bias,
                                 float* __restrict__ outp, int emit) {
    int n = blockIdx.x;
    int tid = threadIdx.x;                  // 128
    int start = g_rowptr[n], end = g_rowptr[n + 1];

    __shared__ float s_m[HH];
    __shared__ float s_rd[HH];
    __shared__ float s_alpha[32][HH];
    __shared__ int   s_src[32];

    const float4* as4 = (const float4*)g_as;
    float4 adv = ((const float4*)g_ad)[n];
    float adh[HH] = {adv.x, adv.y, adv.z, adv.w};

    if (tid < 32) {
        float m[HH] = {-1e30f, -1e30f, -1e30f, -1e30f};
        float d[HH] = {0.f, 0.f, 0.f, 0.f};
        for (int j = start + tid; j < end; j += 32) {
            int s = g_col[j];
            float4 av = as4[s];
            float ee[HH] = {av.x + adh[0], av.y + adh[1], av.z + adh[2], av.w + adh[3]};
            #pragma unroll
            for (int hd = 0; hd < HH; hd++) {
                float e = ee[hd];
                e = (e > 0.f) ? e : 0.2f * e;
                float nm = fmaxf(m[hd], e);
                d[hd] = d[hd] * __expf(m[hd] - nm) + __expf(e - nm);
                m[hd] = nm;
            }
        }
        #pragma unroll
        for (int off = 16; off > 0; off >>= 1) {
            #pragma unroll
            for (int hd = 0; hd < HH; hd++) {
                float om = __shfl_xor_sync(0xffffffffu, m[hd], off);
                float od = __shfl_xor_sync(0xffffffffu, d[hd], off);
                float nm = fmaxf(m[hd], om);
                d[hd] = d[hd] * __expf(m[hd] - nm) + od * __expf(om - nm);
                m[hd] = nm;
            }
        }
        if (tid < HH) {
            s_m[tid] = m[tid];
            s_rd[tid] = 1.f / (d[tid] + 1e-16f);
        }
    }
    __syncthreads();

    float accA0 = 0.f, accA1 = 0.f, accB0 = 0.f, accB1 = 0.f;
    int c0 = 2 * tid;
    int myh = tid >> 5;
    for (int base = start; base < end; base += 32) {
        int cnt = min(32, end - base);
        if (tid < cnt) {
            int s = g_col[base + tid];
            s_src[tid] = s;
            float4 av = as4[s];
            float ee[HH] = {av.x + adh[0], av.y + adh[1], av.z + adh[2], av.w + adh[3]};
            #pragma unroll
            for (int hd = 0; hd < HH; hd++) {
                float e = ee[hd];
                e = (e > 0.f) ? e : 0.2f * e;
                s_alpha[tid][hd] = __expf(e - s_m[hd]) * s_rd[hd];
            }
        }
        __syncthreads();
        int k = 0;
        for (; k + 2 <= cnt; k += 2) {
            int sA = s_src[k], sB = s_src[k + 1];
            float aA = s_alpha[k][myh], aB = s_alpha[k + 1][myh];
            float2 hA = *(const float2*)(h + (size_t)sA * FH + c0);
            float2 hB = *(const float2*)(h + (size_t)sB * FH + c0);
            accA0 = fmaf(hA.x, aA, accA0);
            accA1 = fmaf(hA.y, aA, accA1);
            accB0 = fmaf(hB.x, aB, accB0);
            accB1 = fmaf(hB.y, aB, accB1);
        }
        if (k < cnt) {
            int sA = s_src[k];
            float aA = s_alpha[k][myh];
            float2 hA = *(const float2*)(h + (size_t)sA * FH + c0);
            accA0 = fmaf(hA.x, aA, accA0);
            accA1 = fmaf(hA.y, aA, accA1);
        }
        __syncthreads();
    }
    float o0 = accA0 + accB0 + bias[c0];
    float o1 = accA1 + accB1 + bias[c0 + 1];
    outp[(size_t)n * FH + c0]     = o0;
    outp[(size_t)n * FH + c0 + 1] = o1;
    if (emit) {
        unsigned hi, lo;
        split2(o0, o1, hi, lo);
        int base = afrag_idx(n, tid, 16);   // kpair p == tid
        g_af2[base] = hi;
        g_af2[base + 4] = lo;
    }
}

// ---------------- pooling ---------------------------------------------------
__global__ void count_kernel(const int* __restrict__ batch) {
    __shared__ int s[256];
    int b = blockIdx.x, tid = threadIdx.x;
    int c = 0;
    for (int i = tid; i < NN; i += 256) c += (batch[i] == b);
    s[tid] = c;
    __syncthreads();
    for (int off = 128; off > 0; off >>= 1) {
        if (tid < off) s[tid] += s[tid + off];
        __syncthreads();
    }
    if (tid == 0) g_cnt[b] = s[0];
}

__global__ void pool_kernel(const float* __restrict__ outp, const int* __restrict__ batch) {
    int n0 = blockIdx.x * 64;
    int tid = threadIdx.x;                // 256 = channel
    int nend = min(n0 + 64, NN);
    float acc = 0.f;
    int cur = batch[n0];
    for (int n = n0; n < nend; n++) {
        int bb = batch[n];
        if (bb != cur) {
            atomicAdd(&g_pool[cur * FH + tid], acc);
            acc = 0.f; cur = bb;
        }
        acc += outp[(size_t)n * FH + tid];
    }
    atomicAdd(&g_pool[cur * FH + tid], acc);
}

// ---------------- MLP tail ---------------------------------------------------
__global__ void mlp_kernel(const float* __restrict__ lw1, const float* __restrict__ lb1,
                           const float* __restrict__ lw2, const float* __restrict__ lb2,
                           float* __restrict__ out) {
    __shared__ float s_in[FH];
    __shared__ float s_mid[128];
    int g = blockIdx.x, tid = threadIdx.x;   // 128 threads
    float inv = 1.f / fmaxf((float)g_cnt[g], 1.f);
    s_in[tid]       = g_pool[g * FH + tid] * inv;
    s_in[tid + 128] = g_pool[g * FH + tid + 128] * inv;
    __syncthreads();
    float acc = lb1[tid];
    #pragma unroll 8
    for (int k = 0; k < FH; k++) acc = fmaf(s_in[k], lw1[k * 128 + tid], acc);
    s_mid[tid] = fmaxf(acc, 0.f);
    __syncthreads();
    if (tid < 10) {
        float a = lb2[tid];
        #pragma unroll 8
        for (int k = 0; k < 128; k++) a = fmaf(s_mid[k], lw2[k * 10 + tid], a);
        out[g * 10 + tid] = fmaxf(a, 0.f);
    }
}

// ---------------- launch ------------------------------------------------------
extern "C" void kernel_launch(void* const* d_in, const int* in_sizes, int n_in,
                              void* d_out, int out_size) {
    const float* x     = (const float*)d_in[0];
    const float* pos   = (const float*)d_in[1];
    const int*   ei    = (const int*)d_in[2];
    const int*   batch = (const int*)d_in[3];
    const float* W1   = (const float*)d_in[4];
    const float* as1  = (const float*)d_in[5];
    const float* ad1  = (const float*)d_in[6];
    const float* b1   = (const float*)d_in[7];
    const float* W2   = (const float*)d_in[8];
    const float* as2  = (const float*)d_in[9];
    const float* ad2  = (const float*)d_in[10];
    const float* b2   = (const float*)d_in[11];
    const float* lw1  = (const float*)d_in[12];
    const float* lb1  = (const float*)d_in[13];
    const float* lw2  = (const float*)d_in[14];
    const float* lb2  = (const float*)d_in[15];
    float* out = (float*)d_out;

    float *p_b1, *p_b2;
    unsigned *p_af1, *p_af2, *p_bf1, *p_bf2;
    cudaGetSymbolAddress((void**)&p_b1, g_buf1);
    cudaGetSymbolAddress((void**)&p_b2, g_buf2);
    cudaGetSymbolAddress((void**)&p_af1, g_af1);
    cudaGetSymbolAddress((void**)&p_af2, g_af2);
    cudaGetSymbolAddress((void**)&p_bf1, g_bf1);
    cudaGetSymbolAddress((void**)&p_bf2, g_bf2);

    static cudaStream_t s1 = nullptr;
    static cudaEvent_t ev_fork = nullptr, ev_join = nullptr;
    if (!s1) {
        cudaStreamCreateWithFlags(&s1, cudaStreamNonBlocking);
        cudaEventCreateWithFlags(&ev_fork, cudaEventDisableTiming);
        cudaEventCreateWithFlags(&ev_join, cudaEventDisableTiming);
    }

    dim3 gg(157, 2);   // 157*128 rows x 2*128 cols

    // fork side stream off the main (capture) stream
    cudaEventRecord(ev_fork, 0);
    cudaStreamWaitEvent(s1, ev_fork, 0);

    // side stream: frag packers + GEMM1 + count    main stream: CSR build
    convert_x1_frag<<<(NN * 32 + 255) / 256, 256, 0, s1>>>(x, pos);
    convert_w_frag<<<(FH * 32 + 255) / 256, 256, 0, s1>>>(W1, 32, 4, p_bf1);
    convert_w_frag<<<(FH * 128 + 255) / 256, 256, 0, s1>>>(W2, 128, 16, p_bf2);
    mma_gemm<<<gg, 256, 0, s1>>>(p_af1, p_bf1, p_b1, 4, as1, ad1);
    count_kernel<<<BG, 256, 0, s1>>>(batch);

    init_zero_kernel<<<(NN + 255) / 256, 256>>>();
    hist_kernel<<<(EE + 255) / 256, 256>>>(ei);
    scan_selfloop_kernel<<<1, 1024>>>();
    scatter_kernel<<<(EE + 255) / 256, 256>>>(ei);

    // join
    cudaEventRecord(ev_join, s1);
    cudaStreamWaitEvent(0, ev_join, 0);

    // ---- GAT layer 1 aggregation (also packs layer-2 A frags) ----
    aggregate_kernel<<<NN, 128>>>(p_b1, b1, p_b2, 1);

    // ---- GAT layer 2 ----
    mma_gemm<<<gg, 256>>>(p_af2, p_bf2, p_b1, 16, as2, ad2);
    aggregate_kernel<<<NN, 128>>>(p_b1, b2, p_b2, 0);

    // ---- pool + MLP ----
    pool_kernel<<<(NN + 63) / 64, 256>>>(p_b2, batch);
    mlp_kernel<<<BG, 128>>>(lw1, lb1, lw2, lb2, out);
}

// round 9
// speedup vs baseline: 1.6794x; 1.1051x over previous
#include <cuda_runtime.h>
#include <cuda_bf16.h>
#include <cuda_fp16.h>
#include <math.h>

#define NN 20000
#define EE 320000
#define ET 340000   // EE + NN self loops
#define BG 32
#define FH 256      // H*C
#define HH 4
#define CC 64
#define NM16 1256   // 157*8 m16-tiles

// ---------------- scratch (device globals; no allocation allowed) ----------
__device__ __align__(16) __half g_h16[NN * FH];    // GEMM output h (fp16 copy, gather source)
__device__ __align__(16) float g_buf2[NN * FH];    // aggregation output (layer 2)
__device__ __align__(16) float g_as[NN * HH];
__device__ __align__(16) float g_ad[NN * HH];
__device__ __align__(16) int   g_deg[NN];
__device__ __align__(16) int   g_rowptr[NN + 1];
__device__ int   g_cursor[NN];
__device__ int   g_col[ET];
__device__ float g_pool[BG * FH];
__device__ int   g_cnt[BG];
// pre-packed mma fragments (m16n8k16 register layout), hi/lo split-bf16
__device__ __align__(16) unsigned g_af1[NM16 * 4 * 32 * 8];    // A layer1, K=64  (4 k16)
__device__ __align__(16) unsigned g_af2[NM16 * 16 * 32 * 8];   // A layer2, K=256 (16 k16)
__device__ __align__(16) unsigned g_bf1[32 * 4 * 32 * 4];      // B=W1^T frags
__device__ __align__(16) unsigned g_bf2[32 * 16 * 32 * 4];     // B=W2^T frags

// ---------------- fragment index helpers ------------------------------------
__device__ __forceinline__ int afrag_idx(int row, int p, int nk16) {
    int m16 = row >> 4, k16 = p >> 3;
    int lane = 4 * (row & 7) + (p & 3);
    int reg  = ((row >> 3) & 1) + 2 * ((p >> 2) & 1);
    return (((m16 * nk16) + k16) * 32 + lane) * 8 + reg;   // hi; lo at +4
}
__device__ __forceinline__ int bfrag_idx(int n, int p, int nk16) {
    int nt = n >> 3, k16 = p >> 3;
    int lane = 4 * (n & 7) + (p & 3);
    int reg = (p >> 2) & 1;
    return ((nt * nk16 + k16) * 32 + lane) * 4 + reg;      // hi; lo at +2
}
__device__ __forceinline__ void split2(float v0, float v1, unsigned &hi, unsigned &lo) {
    __nv_bfloat16 h0 = __float2bfloat16(v0), h1 = __float2bfloat16(v1);
    __nv_bfloat16 l0 = __float2bfloat16(v0 - __bfloat162float(h0));
    __nv_bfloat16 l1 = __float2bfloat16(v1 - __bfloat162float(h1));
    __nv_bfloat162 hh; hh.x = h0; hh.y = h1;
    __nv_bfloat162 ll; ll.x = l0; ll.y = l1;
    hi = *(unsigned*)&hh;
    lo = *(unsigned*)&ll;
}
__device__ __forceinline__ void mma16816(float* d, unsigned a0, unsigned a1, unsigned a2,
                                         unsigned a3, unsigned b0, unsigned b1) {
    asm volatile("mma.sync.aligned.m16n8k16.row.col.f32.bf16.bf16.f32 "
        "{%0,%1,%2,%3}, {%4,%5,%6,%7}, {%8,%9}, {%0,%1,%2,%3};"
        : "+f"(d[0]), "+f"(d[1]), "+f"(d[2]), "+f"(d[3])
        : "r"(a0), "r"(a1), "r"(a2), "r"(a3), "r"(b0), "r"(b1));
}

// ---------------- init / CSR build -----------------------------------------
__global__ void init_zero_kernel() {
    int n = blockIdx.x * blockDim.x + threadIdx.x;
    if (n < NN) g_deg[n] = 1;
    if (n < BG * FH) g_pool[n] = 0.f;
    if (n < BG) g_cnt[n] = 0;
}

__global__ void hist_kernel(const int* __restrict__ ei) {
    int e = blockIdx.x * blockDim.x + threadIdx.x;
    if (e >= EE) return;
    atomicAdd(&g_deg[ei[EE + e]], 1);
}

__global__ void scan_selfloop_kernel() {
    __shared__ int wsum[32];
    int tid = threadIdx.x;
    int lane = tid & 31, wid = tid >> 5;
    int4 v[5];
    int sum = 0;
    if (tid < 1000) {
        const int4* p = (const int4*)(g_deg + tid * 20);
        #pragma unroll
        for (int i = 0; i < 5; i++) { v[i] = p[i]; sum += v[i].x + v[i].y + v[i].z + v[i].w; }
    }
    int inc = sum;
    #pragma unroll
    for (int off = 1; off < 32; off <<= 1) {
        int u = __shfl_up_sync(0xffffffffu, inc, off);
        if (lane >= off) inc += u;
    }
    if (lane == 31) wsum[wid] = inc;
    __syncthreads();
    if (wid == 0) {
        int w = wsum[lane];
        #pragma unroll
        for (int off = 1; off < 32; off <<= 1) {
            int u = __shfl_up_sync(0xffffffffu, w, off);
            if (lane >= off) w += u;
        }
        wsum[lane] = w;
    }
    __syncthreads();
    int excl = inc - sum + (wid ? wsum[wid - 1] : 0);
    if (tid < 1000) {
        int run = excl;
        int base = tid * 20;
        int4* q = (int4*)(g_rowptr + base);
        #pragma unroll
        for (int i = 0; i < 5; i++) {
            int4 o;
            int n0 = base + i * 4;
            o.x = run; g_col[run] = n0;     g_cursor[n0]     = run + 1; run += v[i].x;
            o.y = run; g_col[run] = n0 + 1; g_cursor[n0 + 1] = run + 1; run += v[i].y;
            o.z = run; g_col[run] = n0 + 2; g_cursor[n0 + 2] = run + 1; run += v[i].z;
            o.w = run; g_col[run] = n0 + 3; g_cursor[n0 + 3] = run + 1; run += v[i].w;
            q[i] = o;
        }
    }
    if (tid == 0) g_rowptr[NN] = wsum[31];
}

__global__ void scatter_kernel(const int* __restrict__ ei) {
    int e = blockIdx.x * blockDim.x + threadIdx.x;
    if (e >= EE) return;
    int src = ei[e];
    int dst = ei[EE + e];
    int p = atomicAdd(&g_cursor[dst], 1);
    g_col[p] = src;
}

// ---------------- fragment packers ------------------------------------------
__global__ void convert_x1_frag(const float* __restrict__ x, const float* __restrict__ pos) {
    int idx = blockIdx.x * blockDim.x + threadIdx.x;
    if (idx >= NN * 32) return;
    int row = idx >> 5, p = idx & 31;
    int k = 2 * p;
    float v0 = (k == 0) ? pos[row * 2]     : x[(size_t)row * 62 + k - 2];
    float v1 = (k == 0) ? pos[row * 2 + 1] : x[(size_t)row * 62 + k - 1];
    unsigned hi, lo;
    split2(v0, v1, hi, lo);
    int base = afrag_idx(row, p, 4);
    g_af1[base] = hi;
    g_af1[base + 4] = lo;
}

__global__ void convert_w_frag(const float* __restrict__ W, int np, int nk16,
                               unsigned* __restrict__ out) {
    int idx = blockIdx.x * blockDim.x + threadIdx.x;
    if (idx >= FH * np) return;
    int n = idx / np, p = idx - n * np;
    float v0 = W[(size_t)(2 * p) * FH + n];
    float v1 = W[(size_t)(2 * p + 1) * FH + n];
    unsigned hi, lo;
    split2(v0, v1, hi, lo);
    int base = bfrag_idx(n, p, nk16);
    out[base] = hi;
    out[base + 2] = lo;
}

// ---------------- mma.sync split-bf16 GEMM + fused alpha dots ----------------
// h16[NN,256] = A @ B^T (fp16 output). 256 thr = 8 warps (4m x 2n), tile 128x128.
template <int NK>
__global__ void __launch_bounds__(256, 2)
mma_gemm(const unsigned* __restrict__ Af, const unsigned* __restrict__ Bf,
         __half* __restrict__ H16,
         const float* __restrict__ a_src, const float* __restrict__ a_dst) {
    __shared__ float s_as[128], s_ad[128];
    int tid = threadIdx.x, lane = tid & 31, w = tid >> 5;
    int bm = blockIdx.x * 128, bn = blockIdx.y * 128;
    int wm = w & 3, wn = w >> 2;
    if (tid < 128) { s_as[tid] = a_src[bn + tid]; s_ad[tid] = a_dst[bn + tid]; }
    __syncthreads();

    int mt0 = (bm >> 4) + wm * 2;
    int nt0 = (bn >> 3) + wn * 8;

    float acc[2][8][4];
    #pragma unroll
    for (int i = 0; i < 2; i++)
        #pragma unroll
        for (int j = 0; j < 8; j++)
            #pragma unroll
            for (int r = 0; r < 4; r++) acc[i][j][r] = 0.f;

    #pragma unroll 2
    for (int k16 = 0; k16 < NK; k16++) {
        const uint4* pa0 = (const uint4*)(Af + ((size_t)(mt0 * NK + k16) * 32 + lane) * 8);
        const uint4* pa1 = (const uint4*)(Af + ((size_t)((mt0 + 1) * NK + k16) * 32 + lane) * 8);
        uint4 ah0 = pa0[0], al0 = pa0[1];
        uint4 ah1 = pa1[0], al1 = pa1[1];
        #pragma unroll
        for (int nt = 0; nt < 8; nt++) {
            uint4 b = *(const uint4*)(Bf + ((size_t)((nt0 + nt) * NK + k16) * 32 + lane) * 4);
            mma16816(acc[0][nt], ah0.x, ah0.y, ah0.z, ah0.w, b.x, b.y);
            mma16816(acc[0][nt], al0.x, al0.y, al0.z, al0.w, b.x, b.y);
            mma16816(acc[0][nt], ah0.x, ah0.y, ah0.z, ah0.w, b.z, b.w);
            mma16816(acc[1][nt], ah1.x, ah1.y, ah1.z, ah1.w, b.x, b.y);
            mma16816(acc[1][nt], al1.x, al1.y, al1.z, al1.w, b.x, b.y);
            mma16816(acc[1][nt], ah1.x, ah1.y, ah1.z, ah1.w, b.z, b.w);
        }
    }

    // epilogue: fp16 h writes + per-head alpha dots (warp n-tile == one head)
    int q = lane >> 2, c2 = (lane & 3) * 2;
    int head = (bn + wn * 64) >> 6;
    #pragma unroll
    for (int mi = 0; mi < 2; mi++) {
        int r0 = bm + wm * 32 + mi * 16 + q;
        int r1 = r0 + 8;
        float ps0 = 0.f, pd0 = 0.f, ps1 = 0.f, pd1 = 0.f;
        #pragma unroll
        for (int nt = 0; nt < 8; nt++) {
            int nl = wn * 64 + nt * 8 + c2;
            float as0 = s_as[nl], as1 = s_as[nl + 1];
            float ad0 = s_ad[nl], ad1 = s_ad[nl + 1];
            ps0 += acc[mi][nt][0] * as0 + acc[mi][nt][1] * as1;
            pd0 += acc[mi][nt][0] * ad0 + acc[mi][nt][1] * ad1;
            ps1 += acc[mi][nt][2] * as0 + acc[mi][nt][3] * as1;
            pd1 += acc[mi][nt][2] * ad0 + acc[mi][nt][3] * ad1;
        }
        #pragma unroll
        for (int s = 1; s < 4; s <<= 1) {
            ps0 += __shfl_xor_sync(0xffffffffu, ps0, s);
            pd0 += __shfl_xor_sync(0xffffffffu, pd0, s);
            ps1 += __shfl_xor_sync(0xffffffffu, ps1, s);
            pd1 += __shfl_xor_sync(0xffffffffu, pd1, s);
        }
        if ((lane & 3) == 0) {
            if (r0 < NN) { g_as[r0 * HH + head] = ps0; g_ad[r0 * HH + head] = pd0; }
            if (r1 < NN) { g_as[r1 * HH + head] = ps1; g_ad[r1 * HH + head] = pd1; }
        }
        if (r0 < NN) {
            __half* hp = H16 + (size_t)r0 * FH + bn + wn * 64 + c2;
            #pragma unroll
            for (int nt = 0; nt < 8; nt++)
                *(__half2*)(hp + nt * 8) = __floats2half2_rn(acc[mi][nt][0], acc[mi][nt][1]);
        }
        if (r1 < NN) {
            __half* hp = H16 + (size_t)r1 * FH + bn + wn * 64 + c2;
            #pragma unroll
            for (int nt = 0; nt < 8; nt++)
                *(__half2*)(hp + nt * 8) = __floats2half2_rn(acc[mi][nt][2], acc[mi][nt][3]);
        }
    }
}

// ---------------- attention aggregation: one block per dst node -------------
// warp 0: online softmax stats; 128 threads: fp16 weighted gather (2 ch/thread).
// emit!=0: pack layer-2 A fragments instead of fp32 outp.
__global__ void aggregate_kernel(const __half* __restrict__ h16, const float* __restrict__ bias,
                                 float* __restrict__ outp, int emit) {
    int n = blockIdx.x;
    int tid = threadIdx.x;                  // 128
    int start = g_rowptr[n], end = g_rowptr[n + 1];

    __shared__ float s_m[HH];
    __shared__ float s_rd[HH];
    __shared__ float s_alpha[32][HH];
    __shared__ int   s_src[32];

    const float4* as4 = (const float4*)g_as;
    float4 adv = ((const float4*)g_ad)[n];
    float adh[HH] = {adv.x, adv.y, adv.z, adv.w};

    if (tid < 32) {
        float m[HH] = {-1e30f, -1e30f, -1e30f, -1e30f};
        float d[HH] = {0.f, 0.f, 0.f, 0.f};
        for (int j = start + tid; j < end; j += 32) {
            int s = g_col[j];
            float4 av = as4[s];
            float ee[HH] = {av.x + adh[0], av.y + adh[1], av.z + adh[2], av.w + adh[3]};
            #pragma unroll
            for (int hd = 0; hd < HH; hd++) {
                float e = ee[hd];
                e = (e > 0.f) ? e : 0.2f * e;
                float nm = fmaxf(m[hd], e);
                d[hd] = d[hd] * __expf(m[hd] - nm) + __expf(e - nm);
                m[hd] = nm;
            }
        }
        #pragma unroll
        for (int off = 16; off > 0; off >>= 1) {
            #pragma unroll
            for (int hd = 0; hd < HH; hd++) {
                float om = __shfl_xor_sync(0xffffffffu, m[hd], off);
                float od = __shfl_xor_sync(0xffffffffu, d[hd], off);
                float nm = fmaxf(m[hd], om);
                d[hd] = d[hd] * __expf(m[hd] - nm) + od * __expf(om - nm);
                m[hd] = nm;
            }
        }
        if (tid < HH) {
            s_m[tid] = m[tid];
            s_rd[tid] = 1.f / (d[tid] + 1e-16f);
        }
    }
    __syncthreads();

    float accA0 = 0.f, accA1 = 0.f, accB0 = 0.f, accB1 = 0.f;
    int c0 = 2 * tid;
    int myh = tid >> 5;
    for (int base = start; base < end; base += 32) {
        int cnt = min(32, end - base);
        if (tid < cnt) {
            int s = g_col[base + tid];
            s_src[tid] = s;
            float4 av = as4[s];
            float ee[HH] = {av.x + adh[0], av.y + adh[1], av.z + adh[2], av.w + adh[3]};
            #pragma unroll
            for (int hd = 0; hd < HH; hd++) {
                float e = ee[hd];
                e = (e > 0.f) ? e : 0.2f * e;
                s_alpha[tid][hd] = __expf(e - s_m[hd]) * s_rd[hd];
            }
        }
        __syncthreads();
        int k = 0;
        for (; k + 2 <= cnt; k += 2) {
            int sA = s_src[k], sB = s_src[k + 1];
            float aA = s_alpha[k][myh], aB = s_alpha[k + 1][myh];
            float2 hA = __half22float2(*(const __half2*)(h16 + (size_t)sA * FH + c0));
            float2 hB = __half22float2(*(const __half2*)(h16 + (size_t)sB * FH + c0));
            accA0 = fmaf(hA.x, aA, accA0);
            accA1 = fmaf(hA.y, aA, accA1);
            accB0 = fmaf(hB.x, aB, accB0);
            accB1 = fmaf(hB.y, aB, accB1);
        }
        if (k < cnt) {
            int sA = s_src[k];
            float aA = s_alpha[k][myh];
            float2 hA = __half22float2(*(const __half2*)(h16 + (size_t)sA * FH + c0));
            accA0 = fmaf(hA.x, aA, accA0);
            accA1 = fmaf(hA.y, aA, accA1);
        }
        __syncthreads();
    }
    float o0 = accA0 + accB0 + bias[c0];
    float o1 = accA1 + accB1 + bias[c0 + 1];
    if (emit) {
        unsigned hi, lo;
        split2(o0, o1, hi, lo);
        int base = afrag_idx(n, tid, 16);   // kpair p == tid
        g_af2[base] = hi;
        g_af2[base + 4] = lo;
    } else {
        outp[(size_t)n * FH + c0]     = o0;
        outp[(size_t)n * FH + c0 + 1] = o1;
    }
}

// ---------------- pooling ---------------------------------------------------
__global__ void count_kernel(const int* __restrict__ batch) {
    __shared__ int s[256];
    int b = blockIdx.x, tid = threadIdx.x;
    int c = 0;
    for (int i = tid; i < NN; i += 256) c += (batch[i] == b);
    s[tid] = c;
    __syncthreads();
    for (int off = 128; off > 0; off >>= 1) {
        if (tid < off) s[tid] += s[tid + off];
        __syncthreads();
    }
    if (tid == 0) g_cnt[b] = s[0];
}

__global__ void pool_kernel(const float* __restrict__ outp, const int* __restrict__ batch) {
    int n0 = blockIdx.x * 64;
    int tid = threadIdx.x;                // 256 = channel
    int nend = min(n0 + 64, NN);
    float acc = 0.f;
    int cur = batch[n0];
    for (int n = n0; n < nend; n++) {
        int bb = batch[n];
        if (bb != cur) {
            atomicAdd(&g_pool[cur * FH + tid], acc);
            acc = 0.f; cur = bb;
        }
        acc += outp[(size_t)n * FH + tid];
    }
    atomicAdd(&g_pool[cur * FH + tid], acc);
}

// ---------------- MLP tail ---------------------------------------------------
__global__ void mlp_kernel(const float* __restrict__ lw1, const float* __restrict__ lb1,
                           const float* __restrict__ lw2, const float* __restrict__ lb2,
                           float* __restrict__ out) {
    __shared__ float s_in[FH];
    __shared__ float s_mid[128];
    int g = blockIdx.x, tid = threadIdx.x;   // 128 threads
    float inv = 1.f / fmaxf((float)g_cnt[g], 1.f);
    s_in[tid]       = g_pool[g * FH + tid] * inv;
    s_in[tid + 128] = g_pool[g * FH + tid + 128] * inv;
    __syncthreads();
    float acc = lb1[tid];
    #pragma unroll 8
    for (int k = 0; k < FH; k++) acc = fmaf(s_in[k], lw1[k * 128 + tid], acc);
    s_mid[tid] = fmaxf(acc, 0.f);
    __syncthreads();
    if (tid < 10) {
        float a = lb2[tid];
        #pragma unroll 8
        for (int k = 0; k < 128; k++) a = fmaf(s_mid[k], lw2[k * 10 + tid], a);
        out[g * 10 + tid] = fmaxf(a, 0.f);
    }
}

// ---------------- launch ------------------------------------------------------
extern "C" void kernel_launch(void* const* d_in, const int* in_sizes, int n_in,
                              void* d_out, int out_size) {
    const float* x     = (const float*)d_in[0];
    const float* pos   = (const float*)d_in[1];
    const int*   ei    = (const int*)d_in[2];
    const int*   batch = (const int*)d_in[3];
    const float* W1   = (const float*)d_in[4];
    const float* as1  = (const float*)d_in[5];
    const float* ad1  = (const float*)d_in[6];
    const float* b1   = (const float*)d_in[7];
    const float* W2   = (const float*)d_in[8];
    const float* as2  = (const float*)d_in[9];
    const float* ad2  = (const float*)d_in[10];
    const float* b2   = (const float*)d_in[11];
    const float* lw1  = (const float*)d_in[12];
    const float* lb1  = (const float*)d_in[13];
    const float* lw2  = (const float*)d_in[14];
    const float* lb2  = (const float*)d_in[15];
    float* out = (float*)d_out;

    float *p_b2;
    __half* p_h16;
    unsigned *p_af1, *p_af2, *p_bf1, *p_bf2;
    cudaGetSymbolAddress((void**)&p_b2, g_buf2);
    cudaGetSymbolAddress((void**)&p_h16, g_h16);
    cudaGetSymbolAddress((void**)&p_af1, g_af1);
    cudaGetSymbolAddress((void**)&p_af2, g_af2);
    cudaGetSymbolAddress((void**)&p_bf1, g_bf1);
    cudaGetSymbolAddress((void**)&p_bf2, g_bf2);

    static cudaStream_t s1 = nullptr;
    static cudaEvent_t ev_fork = nullptr, ev_join = nullptr;
    if (!s1) {
        cudaStreamCreateWithFlags(&s1, cudaStreamNonBlocking);
        cudaEventCreateWithFlags(&ev_fork, cudaEventDisableTiming);
        cudaEventCreateWithFlags(&ev_join, cudaEventDisableTiming);
    }

    dim3 gg(157, 2);   // 157*128 rows x 2*128 cols

    // fork side stream off the main (capture) stream
    cudaEventRecord(ev_fork, 0);
    cudaStreamWaitEvent(s1, ev_fork, 0);

    // side stream: frag packers + GEMM1 + count    main stream: CSR build
    convert_x1_frag<<<(NN * 32 + 255) / 256, 256, 0, s1>>>(x, pos);
    convert_w_frag<<<(FH * 32 + 255) / 256, 256, 0, s1>>>(W1, 32, 4, p_bf1);
    convert_w_frag<<<(FH * 128 + 255) / 256, 256, 0, s1>>>(W2, 128, 16, p_bf2);
    mma_gemm<4><<<gg, 256, 0, s1>>>(p_af1, p_bf1, p_h16, as1, ad1);
    count_kernel<<<BG, 256, 0, s1>>>(batch);

    init_zero_kernel<<<(NN + 255) / 256, 256>>>();
    hist_kernel<<<(EE + 255) / 256, 256>>>(ei);
    scan_selfloop_kernel<<<1, 1024>>>();
    scatter_kernel<<<(EE + 255) / 256, 256>>>(ei);

    // join
    cudaEventRecord(ev_join, s1);
    cudaStreamWaitEvent(0, ev_join, 0);

    // ---- GAT layer 1 aggregation (packs layer-2 A frags) ----
    aggregate_kernel<<<NN, 128>>>(p_h16, b1, p_b2, 1);

    // ---- GAT layer 2 ----
    mma_gemm<16><<<gg, 256>>>(p_af2, p_bf2, p_h16, as2, ad2);
    aggregate_kernel<<<NN, 128>>>(p_h16, b2, p_b2, 0);

    // ---- pool + MLP ----
    pool_kernel<<<(NN + 63) / 64, 256>>>(p_b2, batch);
    mlp_kernel<<<BG, 128>>>(lw1, lb1, lw2, lb2, out);
}